// round 7
// baseline (speedup 1.0000x reference)
#include <cuda_runtime.h>
#include <math.h>
#include <stdint.h>

// Problem constants
#define Nn   4096
#define Mm   2048
#define IS   128
#define XC   129
#define INDIM 257
#define QDIM 32
#define CATP 288
#define KG   8224
#define NT   258

#define S_GATE 12
#define S_C    24
#define S_G1   8

__device__ float g_cat [Nn * CATP];
__device__ float g_cgT [CATP * Mm];
__device__ float g_cnT [CATP * Mm];
__device__ float g_r   [Mm * IS];
__device__ float g_u   [Mm * IS];
__device__ float g_pg1 [S_G1 * CATP * Mm];
__device__ float g_pr  [S_GATE * Mm * IS];
__device__ float g_pu  [S_GATE * Mm * IS];
__device__ float g_pc  [S_C * Mm * IS];

typedef unsigned long long ull;

__device__ __forceinline__ void fma2(ull &c, ull a, ull b) {
    asm("fma.rn.f32x2 %0, %1, %2, %0;" : "+l"(c) : "l"(a), "l"(b));
}
__device__ __forceinline__ ull pack2(float x, float y) {
    ull r; asm("mov.b64 %0, {%1, %2};" : "=l"(r) : "f"(x), "f"(y)); return r;
}
__device__ __forceinline__ float2 unpack2(ull v) {
    float2 f; asm("mov.b64 {%0, %1}, %2;" : "=f"(f.x), "=f"(f.y) : "l"(v)); return f;
}
__device__ __forceinline__ float sigmoidf_(float v) {
    return 1.0f / (1.0f + expf(-v));
}
__device__ __forceinline__ void cpa16(uint32_t dst, const void* src) {
    asm volatile("cp.async.ca.shared.global [%0], [%1], 16;" :: "r"(dst), "l"(src));
}
#define CP_COMMIT() asm volatile("cp.async.commit_group;")
#define CP_WAIT0()  asm volatile("cp.async.wait_group 0;")

// ---------------------------------------------------------------------------
__global__ void k_pack_cat(const float* __restrict__ x, const float* __restrict__ h) {
    int idx = blockIdx.x * 256 + threadIdx.x;
    if (idx >= Nn * CATP) return;
    int row = idx / CATP;
    int c   = idx - row * CATP;
    float v = 0.0f;
    if (c < XC)        v = x[row * XC + c];
    else if (c < INDIM) v = h[row * IS + (c - XC)];
    g_cat[idx] = v;
}

// ---------------------------------------------------------------------------
// GEMM1: BM=128, BN=96, BK=32. grid (3, 16, S_G1), 256 thr, 8m x 6n.
// ---------------------------------------------------------------------------
__global__ __launch_bounds__(256, 2) void k_gemm1(const float* __restrict__ adj,
                                                  const int* __restrict__ nodes) {
    __shared__ float As[2][32][132];   // row = 528B, 16B-aligned
    __shared__ float Bs[2][32][96];    // row = 384B
    __shared__ int rows[128];

    int t  = threadIdx.x;
    int m0 = blockIdx.y * 128;
    int n0 = blockIdx.x * 96;
    int s  = blockIdx.z;
    if (t < 128) rows[t] = nodes[m0 + t];
    __syncthreads();

    int w = t >> 5, lane = t & 31;
    int tx = t & 15, ty = t >> 4;

    uint32_t bs_base = (uint32_t)__cvta_generic_to_shared(&Bs[0][0][0]);

    ull acc[8][3];
#pragma unroll
    for (int r = 0; r < 8; r++)
#pragma unroll
        for (int j = 0; j < 3; j++) acc[r][j] = 0ULL;

    const int kbeg = s * (Nn / S_G1);
    const int niter = (Nn / S_G1) / 32;   // 16

    float4 a4[4];
#define G1_LDA(K0)                                                            \
    _Pragma("unroll")                                                         \
    for (int pp = 0; pp < 4; pp++) {                                          \
        int row = lane + 32 * pp;                                             \
        a4[pp] = *(const float4*)&adj[(size_t)rows[row] * Nn + (K0) + w * 4]; \
    }
#define G1_STA(NB)                                                            \
    _Pragma("unroll")                                                         \
    for (int pp = 0; pp < 4; pp++) {                                          \
        int row = lane + 32 * pp;                                             \
        As[NB][w * 4 + 0][row] = a4[pp].x;                                    \
        As[NB][w * 4 + 1][row] = a4[pp].y;                                    \
        As[NB][w * 4 + 2][row] = a4[pp].z;                                    \
        As[NB][w * 4 + 3][row] = a4[pp].w;                                    \
    }
#define G1_LDB(K0, NB)                                                        \
    _Pragma("unroll")                                                         \
    for (int p = 0; p < 3; p++) {                                             \
        int e = t + 256 * p;                                                  \
        int row = e / 24, c = e - row * 24;                                   \
        cpa16(bs_base + (uint32_t)((NB) * 12288 + row * 384 + c * 16),        \
              &g_cat[(size_t)((K0) + row) * CATP + n0 + c * 4]);              \
    }

    G1_LDA(kbeg);
    G1_LDB(kbeg, 0);
    CP_COMMIT();
    G1_STA(0);
    CP_WAIT0();
    __syncthreads();

    for (int it = 0; it < niter; it++) {
        int buf = it & 1, nb = buf ^ 1;
        bool has = (it + 1 < niter);
        if (has) {
            int k0 = kbeg + (it + 1) * 32;
            G1_LDA(k0);
            G1_LDB(k0, nb);
            CP_COMMIT();
        }
#pragma unroll
        for (int kk = 0; kk < 32; kk++) {
            float4 a0 = *(const float4*)&As[buf][kk][ty * 8];
            float4 a1 = *(const float4*)&As[buf][kk][ty * 8 + 4];
            ull b0 = *(const ull*)&Bs[buf][kk][tx * 6 + 0];
            ull b1 = *(const ull*)&Bs[buf][kk][tx * 6 + 2];
            ull b2 = *(const ull*)&Bs[buf][kk][tx * 6 + 4];
            float av[8] = {a0.x, a0.y, a0.z, a0.w, a1.x, a1.y, a1.z, a1.w};
#pragma unroll
            for (int r = 0; r < 8; r++) {
                ull am = pack2(av[r], av[r]);
                fma2(acc[r][0], am, b0);
                fma2(acc[r][1], am, b1);
                fma2(acc[r][2], am, b2);
            }
        }
        if (has) {
            G1_STA(nb);
            CP_WAIT0();
        }
        __syncthreads();
    }

    float* dst = &g_pg1[(size_t)s * CATP * Mm];
    int cb = n0 + tx * 6;
#pragma unroll
    for (int r = 0; r < 8; r++) {
        int m = m0 + ty * 8 + r;
#pragma unroll
        for (int j = 0; j < 3; j++) {
            float2 v = unpack2(acc[r][j]);
            dst[(size_t)(cb + 2 * j + 0) * Mm + m] = v.x;
            dst[(size_t)(cb + 2 * j + 1) * Mm + m] = v.y;
        }
    }
#undef G1_LDA
#undef G1_STA
#undef G1_LDB
}

__global__ void k_g1_reduce() {
    int idx = blockIdx.x * 256 + threadIdx.x;
    if (idx >= CATP * Mm / 4) return;
    const float4* p = (const float4*)g_pg1;
    float4 o = make_float4(0.f, 0.f, 0.f, 0.f);
#pragma unroll
    for (int s = 0; s < S_G1; s++) {
        float4 a = p[idx + (size_t)s * (CATP * Mm / 4)];
        o.x += a.x; o.y += a.y; o.z += a.z; o.w += a.w;
    }
    ((float4*)g_cgT)[idx] = o;
}

// ---------------------------------------------------------------------------
// Gates GEMM: BM=128, BN=64, BK=32. grid (2, 16, S_GATE), 256 thr, 8m x 4n x 2.
// ---------------------------------------------------------------------------
__global__ __launch_bounds__(256, 2) void k_gates(const float* __restrict__ q,
                                                  const float* __restrict__ Wr,
                                                  const float* __restrict__ br,
                                                  const float* __restrict__ Wu,
                                                  const float* __restrict__ bu) {
    __shared__ float qs[128][33];
    __shared__ float Zs[2][32][128];   // row = 512B
    __shared__ float Wrs[2][32][64];   // row = 256B
    __shared__ float Wus[2][32][64];

    int t  = threadIdx.x;
    int m0 = blockIdx.y * 128;
    int n0 = blockIdx.x * 64;
    int s  = blockIdx.z;

#pragma unroll
    for (int p = 0; p < 16; p++) {
        int e = t + 256 * p;
        int m = e >> 5, d = e & 31;
        qs[m][d] = q[(size_t)(m0 + m) * QDIM + d];
    }
    __syncthreads();

    int tx = t & 15, ty = t >> 4;
    int mloc = t & 127;       // staging m
    int kkb  = t >> 7;        // 0..1

    uint32_t wr_base = (uint32_t)__cvta_generic_to_shared(&Wrs[0][0][0]);
    uint32_t wu_base = (uint32_t)__cvta_generic_to_shared(&Wus[0][0][0]);

    ull accr[8][2], accu[8][2];
#pragma unroll
    for (int r = 0; r < 8; r++) {
        accr[r][0] = accr[r][1] = 0ULL;
        accu[r][0] = accu[r][1] = 0ULL;
    }

    const int tbeg = (s * NT) / S_GATE;
    const int tend = ((s + 1) * NT) / S_GATE;
    const int nt_loc = tend - tbeg;
    float zreg[16];

#define STAGE_Z(TILE, SRC)                                                   \
    {                                                                        \
        int _tile = (TILE);                                                  \
        if (_tile < 257) {                                                   \
            int _k0 = _tile * 32;                                            \
            int _d0 = _k0 / INDIM;                                           \
            int _kb = (_d0 + 1) * INDIM;                                     \
            _Pragma("unroll")                                                \
            for (int p = 0; p < 16; p++) {                                   \
                int _k = _k0 + kkb + 2 * p;                                  \
                int _d = (_k >= _kb) ? _d0 + 1 : _d0;                        \
                int _i = _k - _d * INDIM;                                    \
                zreg[p] = qs[mloc][_d] * SRC[(size_t)_i * Mm + m0 + mloc];   \
            }                                                                \
        } else {                                                             \
            _Pragma("unroll")                                                \
            for (int p = 0; p < 16; p++) zreg[p] = qs[mloc][kkb + 2 * p];    \
        }                                                                    \
    }
#define STS_Z(NB)                                                            \
    {                                                                        \
        _Pragma("unroll")                                                    \
        for (int p = 0; p < 16; p++) Zs[NB][kkb + 2 * p][mloc] = zreg[p];    \
    }
#define CPA_W(TILE, NB)                                                      \
    {                                                                        \
        int _tile = (TILE);                                                  \
        int _k0 = _tile * 32;                                                \
        _Pragma("unroll")                                                    \
        for (int p = 0; p < 2; p++) {                                        \
            int e = t + 256 * p;                                             \
            int row = e >> 4, c4 = e & 15;                                   \
            uint32_t off = (uint32_t)((NB) * 8192 + row * 256 + c4 * 16);    \
            if (_tile < 257) {                                               \
                cpa16(wr_base + off, &Wr[(size_t)(_k0 + row) * IS + n0 + c4 * 4]); \
                cpa16(wu_base + off, &Wu[(size_t)(_k0 + row) * IS + n0 + c4 * 4]); \
            } else {                                                         \
                cpa16(wr_base + off, &br[(size_t)row * IS + n0 + c4 * 4]);   \
                cpa16(wu_base + off, &bu[(size_t)row * IS + n0 + c4 * 4]);   \
            }                                                                \
        }                                                                    \
    }

    STAGE_Z(tbeg, g_cgT);
    CPA_W(tbeg, 0);
    CP_COMMIT();
    STS_Z(0);
    CP_WAIT0();
    __syncthreads();

    for (int it = 0; it < nt_loc; it++) {
        int buf = it & 1, nb = buf ^ 1;
        bool has = (it + 1 < nt_loc);
        if (has) {
            STAGE_Z(tbeg + it + 1, g_cgT);
            CPA_W(tbeg + it + 1, nb);
            CP_COMMIT();
        }
#pragma unroll
        for (int kk = 0; kk < 32; kk++) {
            float4 z0 = *(const float4*)&Zs[buf][kk][ty * 8];
            float4 z1 = *(const float4*)&Zs[buf][kk][ty * 8 + 4];
            ulonglong2 wr2 = *(const ulonglong2*)&Wrs[buf][kk][tx * 4];
            ulonglong2 wu2 = *(const ulonglong2*)&Wus[buf][kk][tx * 4];
            float zv[8] = {z0.x, z0.y, z0.z, z0.w, z1.x, z1.y, z1.z, z1.w};
#pragma unroll
            for (int r = 0; r < 8; r++) {
                ull am = pack2(zv[r], zv[r]);
                fma2(accr[r][0], am, wr2.x);
                fma2(accr[r][1], am, wr2.y);
                fma2(accu[r][0], am, wu2.x);
                fma2(accu[r][1], am, wu2.y);
            }
        }
        if (has) {
            STS_Z(nb);
            CP_WAIT0();
        }
        __syncthreads();
    }

    float* dr = &g_pr[(size_t)s * Mm * IS];
    float* du = &g_pu[(size_t)s * Mm * IS];
#pragma unroll
    for (int r = 0; r < 8; r++) {
        int m = m0 + ty * 8 + r;
        float2 r0 = unpack2(accr[r][0]), r1 = unpack2(accr[r][1]);
        float2 u0 = unpack2(accu[r][0]), u1 = unpack2(accu[r][1]);
        *(float4*)&dr[(size_t)m * IS + n0 + tx * 4] = make_float4(r0.x, r0.y, r1.x, r1.y);
        *(float4*)&du[(size_t)m * IS + n0 + tx * 4] = make_float4(u0.x, u0.y, u1.x, u1.y);
    }
}

__global__ void k_gates_reduce() {
    int idx = blockIdx.x * 256 + threadIdx.x;
    if (idx >= Mm * IS / 4) return;
    const float4* pr = (const float4*)g_pr;
    const float4* pu = (const float4*)g_pu;
    float4 r = make_float4(0.f, 0.f, 0.f, 0.f);
    float4 u = make_float4(0.f, 0.f, 0.f, 0.f);
#pragma unroll
    for (int s = 0; s < S_GATE; s++) {
        float4 a = pr[idx + (size_t)s * (Mm * IS / 4)];
        float4 b = pu[idx + (size_t)s * (Mm * IS / 4)];
        r.x += a.x; r.y += a.y; r.z += a.z; r.w += a.w;
        u.x += b.x; u.y += b.y; u.z += b.z; u.w += b.w;
    }
    r.x = sigmoidf_(r.x); r.y = sigmoidf_(r.y); r.z = sigmoidf_(r.z); r.w = sigmoidf_(r.w);
    u.x = sigmoidf_(u.x); u.y = sigmoidf_(u.y); u.z = sigmoidf_(u.z); u.w = sigmoidf_(u.w);
    ((float4*)g_r)[idx] = r;
    ((float4*)g_u)[idx] = u;
}

// ---------------------------------------------------------------------------
__global__ void k_pack_cn(const float* __restrict__ x, const float* __restrict__ h,
                          const int* __restrict__ nodes) {
    int idx = blockIdx.x * 256 + threadIdx.x;
    if (idx >= CATP * Mm) return;
    int i = idx / Mm;
    int m = idx - i * Mm;
    float v = 0.0f;
    if (i < XC) {
        v = x[(size_t)nodes[m] * XC + i];
    } else if (i < INDIM) {
        int j = i - XC;
        v = g_r[(size_t)m * IS + j] * h[(size_t)nodes[m] * IS + j];
    }
    g_cnT[idx] = v;
}

// ---------------------------------------------------------------------------
// Candidate GEMM: BM=128, BN=128, BK=32. grid (1, 16, S_C), 256 thr, 8m x 8n.
// ---------------------------------------------------------------------------
__global__ __launch_bounds__(256, 2) void k_final(const float* __restrict__ q,
                                                  const float* __restrict__ Wc,
                                                  const float* __restrict__ bc) {
    __shared__ float qs[128][33];
    __shared__ float Zs[2][32][128];
    __shared__ float Wcs[2][32][128];  // row = 512B

    int t  = threadIdx.x;
    int m0 = blockIdx.y * 128;
    int n0 = 0;
    int s  = blockIdx.z;

#pragma unroll
    for (int p = 0; p < 16; p++) {
        int e = t + 256 * p;
        int m = e >> 5, d = e & 31;
        qs[m][d] = q[(size_t)(m0 + m) * QDIM + d];
    }
    __syncthreads();

    int tx = t & 15, ty = t >> 4;
    int mloc = t & 127;
    int kkb  = t >> 7;

    uint32_t wc_base = (uint32_t)__cvta_generic_to_shared(&Wcs[0][0][0]);

    ull acc[8][4];
#pragma unroll
    for (int r = 0; r < 8; r++)
#pragma unroll
        for (int j = 0; j < 4; j++) acc[r][j] = 0ULL;

    const int tbeg = (s * NT) / S_C;
    const int tend = ((s + 1) * NT) / S_C;
    const int nt_loc = tend - tbeg;
    float zreg[16];

#define CPA_WC(TILE, NB)                                                     \
    {                                                                        \
        int _tile = (TILE);                                                  \
        int _k0 = _tile * 32;                                                \
        _Pragma("unroll")                                                    \
        for (int p = 0; p < 4; p++) {                                        \
            int e = t + 256 * p;                                             \
            int row = e >> 5, c4 = e & 31;                                   \
            uint32_t off = (uint32_t)((NB) * 16384 + row * 512 + c4 * 16);   \
            if (_tile < 257)                                                 \
                cpa16(wc_base + off, &Wc[(size_t)(_k0 + row) * IS + c4 * 4]); \
            else                                                             \
                cpa16(wc_base + off, &bc[(size_t)row * IS + c4 * 4]);        \
        }                                                                    \
    }

    STAGE_Z(tbeg, g_cnT);
    CPA_WC(tbeg, 0);
    CP_COMMIT();
    STS_Z(0);
    CP_WAIT0();
    __syncthreads();

    for (int it = 0; it < nt_loc; it++) {
        int buf = it & 1, nb = buf ^ 1;
        bool has = (it + 1 < nt_loc);
        if (has) {
            STAGE_Z(tbeg + it + 1, g_cnT);
            CPA_WC(tbeg + it + 1, nb);
            CP_COMMIT();
        }
#pragma unroll
        for (int kk = 0; kk < 32; kk++) {
            float4 z0 = *(const float4*)&Zs[buf][kk][ty * 8];
            float4 z1 = *(const float4*)&Zs[buf][kk][ty * 8 + 4];
            ulonglong2 w0 = *(const ulonglong2*)&Wcs[buf][kk][tx * 8];
            ulonglong2 w1 = *(const ulonglong2*)&Wcs[buf][kk][tx * 8 + 4];
            float zv[8] = {z0.x, z0.y, z0.z, z0.w, z1.x, z1.y, z1.z, z1.w};
#pragma unroll
            for (int r = 0; r < 8; r++) {
                ull am = pack2(zv[r], zv[r]);
                fma2(acc[r][0], am, w0.x);
                fma2(acc[r][1], am, w0.y);
                fma2(acc[r][2], am, w1.x);
                fma2(acc[r][3], am, w1.y);
            }
        }
        if (has) {
            STS_Z(nb);
            CP_WAIT0();
        }
        __syncthreads();
    }

    float* dc = &g_pc[(size_t)s * Mm * IS];
#pragma unroll
    for (int r = 0; r < 8; r++) {
        int m = m0 + ty * 8 + r;
        float2 c0 = unpack2(acc[r][0]), c1 = unpack2(acc[r][1]);
        float2 c2 = unpack2(acc[r][2]), c3 = unpack2(acc[r][3]);
        *(float4*)&dc[(size_t)m * IS + tx * 8 + 0] = make_float4(c0.x, c0.y, c1.x, c1.y);
        *(float4*)&dc[(size_t)m * IS + tx * 8 + 4] = make_float4(c2.x, c2.y, c3.x, c3.y);
    }
#undef CPA_WC
#undef STAGE_Z
#undef STS_Z
#undef CPA_W
}

__global__ void k_final_reduce(const float* __restrict__ h,
                               const int* __restrict__ nodes,
                               float* __restrict__ out) {
    int idx = blockIdx.x * 256 + threadIdx.x;
    if (idx >= Mm * IS / 4) return;
    int m  = idx / (IS / 4);
    int c4 = idx - m * (IS / 4);
    int nm = nodes[m];

    const float4* pc = (const float4*)g_pc;
    float4 c = make_float4(0.f, 0.f, 0.f, 0.f);
#pragma unroll
    for (int s = 0; s < S_C; s++) {
        float4 a = pc[idx + (size_t)s * (Mm * IS / 4)];
        c.x += a.x; c.y += a.y; c.z += a.z; c.w += a.w;
    }
    float4 rr = ((const float4*)g_r)[idx];
    float4 uu = ((const float4*)g_u)[idx];
    float4 hv = *(const float4*)&h[(size_t)nm * IS + c4 * 4];
    float4 o;
    o.x = (1.0f - uu.x) * rr.x * hv.x + uu.x * tanhf(c.x);
    o.y = (1.0f - uu.y) * rr.y * hv.y + uu.y * tanhf(c.y);
    o.z = (1.0f - uu.z) * rr.z * hv.z + uu.z * tanhf(c.z);
    o.w = (1.0f - uu.w) * rr.w * hv.w + uu.w * tanhf(c.w);
    *(float4*)&out[(size_t)m * IS + c4 * 4] = o;
}

// ---------------------------------------------------------------------------
extern "C" void kernel_launch(void* const* d_in, const int* in_sizes, int n_in,
                              void* d_out, int out_size) {
    const float* x    = (const float*)d_in[0];
    const float* h    = (const float*)d_in[1];
    const float* q    = (const float*)d_in[2];
    const float* adj  = (const float*)d_in[3];
    const int*   nodes= (const int*)  d_in[4];
    const float* Wu   = (const float*)d_in[5];
    const float* bu   = (const float*)d_in[6];
    const float* Wr   = (const float*)d_in[7];
    const float* br   = (const float*)d_in[8];
    const float* Wc   = (const float*)d_in[9];
    const float* bc   = (const float*)d_in[10];
    float* out = (float*)d_out;

    k_pack_cat<<<(Nn * CATP + 255) / 256, 256>>>(x, h);
    k_gemm1<<<dim3(3, 16, S_G1), 256>>>(adj, nodes);
    k_g1_reduce<<<(CATP * Mm / 4 + 255) / 256, 256>>>();
    k_gates<<<dim3(2, 16, S_GATE), 256>>>(q, Wr, br, Wu, bu);
    k_gates_reduce<<<(Mm * IS / 4 + 255) / 256, 256>>>();
    k_pack_cn<<<(CATP * Mm + 255) / 256, 256>>>(x, h, nodes);
    k_final<<<dim3(1, 16, S_C), 256>>>(q, Wc, bc);
    k_final_reduce<<<(Mm * IS / 4 + 255) / 256, 256>>>(h, nodes, out);
}

// round 8
// speedup vs baseline: 1.5506x; 1.5506x over previous
#include <cuda_runtime.h>
#include <cuda_bf16.h>
#include <math.h>
#include <stdint.h>

#define Nn   4096
#define Mm   2048
#define IS   128
#define XC   129
#define INDIM 257
#define QDIM 32
#define CATP 288
#define KP   288
#define S_G1 8

typedef unsigned long long ull;
typedef __nv_bfloat16 bf16;

__device__ float g_cat [Nn * CATP];
__device__ float g_pg1 [S_G1 * Mm * CATP];
__device__ __align__(16) bf16 g_cghi[Mm * KP];
__device__ __align__(16) bf16 g_cglo[Mm * KP];
__device__ __align__(16) bf16 g_cnhi[Mm * KP];
__device__ __align__(16) bf16 g_cnlo[Mm * KP];
__device__ __align__(16) bf16 g_Whi[(size_t)3 * 32 * KP * IS];
__device__ __align__(16) bf16 g_Wlo[(size_t)3 * 32 * KP * IS];
__device__ float g_pr [4 * Mm * IS];
__device__ float g_pu [4 * Mm * IS];
__device__ float g_pc [16 * Mm * IS];
__device__ float g_r  [Mm * IS];
__device__ float g_u  [Mm * IS];

__device__ __forceinline__ void fma2(ull &c, ull a, ull b) {
    asm("fma.rn.f32x2 %0, %1, %2, %0;" : "+l"(c) : "l"(a), "l"(b));
}
__device__ __forceinline__ ull pack2(float x, float y) {
    ull r; asm("mov.b64 %0, {%1, %2};" : "=l"(r) : "f"(x), "f"(y)); return r;
}
__device__ __forceinline__ float2 unpack2(ull v) {
    float2 f; asm("mov.b64 {%0, %1}, %2;" : "=f"(f.x), "=f"(f.y) : "l"(v)); return f;
}
__device__ __forceinline__ float sigmoidf_(float v) { return 1.0f / (1.0f + expf(-v)); }
__device__ __forceinline__ void cpa16(uint32_t dst, const void* src) {
    asm volatile("cp.async.ca.shared.global [%0], [%1], 16;" :: "r"(dst), "l"(src));
}
#define CP_COMMIT() asm volatile("cp.async.commit_group;")
#define CP_WAIT0()  asm volatile("cp.async.wait_group 0;")

#define LDSMX4(R, ADDR)                                                       \
    asm volatile("ldmatrix.sync.aligned.m8n8.x4.shared.b16 {%0,%1,%2,%3}, [%4];" \
        : "=r"((R)[0]), "=r"((R)[1]), "=r"((R)[2]), "=r"((R)[3]) : "r"(ADDR))
#define LDSMX4T(R, ADDR)                                                      \
    asm volatile("ldmatrix.sync.aligned.m8n8.x4.trans.shared.b16 {%0,%1,%2,%3}, [%4];" \
        : "=r"((R)[0]), "=r"((R)[1]), "=r"((R)[2]), "=r"((R)[3]) : "r"(ADDR))
#define MMA(C, A, B)                                                          \
    asm volatile("mma.sync.aligned.m16n8k16.row.col.f32.bf16.bf16.f32 "       \
        "{%0,%1,%2,%3}, {%4,%5,%6,%7}, {%8,%9}, {%0,%1,%2,%3};"               \
        : "+f"((C)[0]), "+f"((C)[1]), "+f"((C)[2]), "+f"((C)[3])              \
        : "r"((A)[0]), "r"((A)[1]), "r"((A)[2]), "r"((A)[3]),                 \
          "r"((B)[0]), "r"((B)[1]))

// ---------------------------------------------------------------------------
__global__ void k_pack_cat(const float* __restrict__ x, const float* __restrict__ h) {
    int idx = blockIdx.x * 256 + threadIdx.x;
    if (idx >= Nn * CATP) return;
    int row = idx / CATP;
    int c   = idx - row * CATP;
    float v = 0.0f;
    if (c < XC)        v = x[row * XC + c];
    else if (c < INDIM) v = h[row * IS + (c - XC)];
    g_cat[idx] = v;
}

// ---------------------------------------------------------------------------
// GEMM1 (FFMA, split-K): pg1[s][m][c] = sum_k adj[nodes[m]][k]*cat[k][c]
// ---------------------------------------------------------------------------
__global__ __launch_bounds__(256, 2) void k_gemm1(const float* __restrict__ adj,
                                                  const int* __restrict__ nodes) {
    __shared__ float As[2][32][132];
    __shared__ float Bs[2][32][96];
    __shared__ int rows[128];

    int t  = threadIdx.x;
    int m0 = blockIdx.y * 128;
    int n0 = blockIdx.x * 96;
    int s  = blockIdx.z;
    if (t < 128) rows[t] = nodes[m0 + t];
    __syncthreads();

    int w = t >> 5, lane = t & 31;
    int tx = t & 15, ty = t >> 4;
    uint32_t bs_base = (uint32_t)__cvta_generic_to_shared(&Bs[0][0][0]);

    ull acc[8][3];
#pragma unroll
    for (int r = 0; r < 8; r++)
#pragma unroll
        for (int j = 0; j < 3; j++) acc[r][j] = 0ULL;

    const int kbeg = s * (Nn / S_G1);
    const int niter = (Nn / S_G1) / 32;

    float4 a4[4];
#define G1_LDA(K0)                                                            \
    _Pragma("unroll")                                                         \
    for (int pp = 0; pp < 4; pp++) {                                          \
        int row = lane + 32 * pp;                                             \
        a4[pp] = *(const float4*)&adj[(size_t)rows[row] * Nn + (K0) + w * 4]; \
    }
#define G1_STA(NB)                                                            \
    _Pragma("unroll")                                                         \
    for (int pp = 0; pp < 4; pp++) {                                          \
        int row = lane + 32 * pp;                                             \
        As[NB][w * 4 + 0][row] = a4[pp].x;                                    \
        As[NB][w * 4 + 1][row] = a4[pp].y;                                    \
        As[NB][w * 4 + 2][row] = a4[pp].z;                                    \
        As[NB][w * 4 + 3][row] = a4[pp].w;                                    \
    }
#define G1_LDB(K0, NB)                                                        \
    _Pragma("unroll")                                                         \
    for (int p = 0; p < 3; p++) {                                             \
        int e = t + 256 * p;                                                  \
        int row = e / 24, c = e - row * 24;                                   \
        cpa16(bs_base + (uint32_t)((NB) * 12288 + row * 384 + c * 16),        \
              &g_cat[(size_t)((K0) + row) * CATP + n0 + c * 4]);              \
    }

    G1_LDA(kbeg);
    G1_LDB(kbeg, 0);
    CP_COMMIT();
    G1_STA(0);
    CP_WAIT0();
    __syncthreads();

    for (int it = 0; it < niter; it++) {
        int buf = it & 1, nb = buf ^ 1;
        bool has = (it + 1 < niter);
        if (has) {
            int k0 = kbeg + (it + 1) * 32;
            G1_LDA(k0);
            G1_LDB(k0, nb);
            CP_COMMIT();
        }
#pragma unroll
        for (int kk = 0; kk < 32; kk++) {
            float4 a0 = *(const float4*)&As[buf][kk][ty * 8];
            float4 a1 = *(const float4*)&As[buf][kk][ty * 8 + 4];
            ull b0 = *(const ull*)&Bs[buf][kk][tx * 6 + 0];
            ull b1 = *(const ull*)&Bs[buf][kk][tx * 6 + 2];
            ull b2 = *(const ull*)&Bs[buf][kk][tx * 6 + 4];
            float av[8] = {a0.x, a0.y, a0.z, a0.w, a1.x, a1.y, a1.z, a1.w};
#pragma unroll
            for (int r = 0; r < 8; r++) {
                ull am = pack2(av[r], av[r]);
                fma2(acc[r][0], am, b0);
                fma2(acc[r][1], am, b1);
                fma2(acc[r][2], am, b2);
            }
        }
        if (has) {
            G1_STA(nb);
            CP_WAIT0();
        }
        __syncthreads();
    }

    float* dst = &g_pg1[(size_t)s * Mm * CATP];
    int cb = n0 + tx * 6;
#pragma unroll
    for (int r = 0; r < 8; r++) {
        int m = m0 + ty * 8 + r;
#pragma unroll
        for (int j = 0; j < 3; j++)
            *(float2*)&dst[(size_t)m * CATP + cb + 2 * j] = unpack2(acc[r][j]);
    }
#undef G1_LDA
#undef G1_STA
#undef G1_LDB
}

// reduce gemm1 partials -> bf16 hi/lo of cg [m][288]; col 257 = 1.0 (bias hook)
__global__ void k_g1_reduce_split() {
    int idx = blockIdx.x * 256 + threadIdx.x;
    if (idx >= Mm * KP) return;
    int m = idx / KP, c = idx - m * KP;
    float v = 0.0f;
    if (c < INDIM) {
#pragma unroll
        for (int s = 0; s < S_G1; s++)
            v += g_pg1[(size_t)s * Mm * CATP + (size_t)m * CATP + c];
    } else if (c == INDIM) v = 1.0f;
    bf16 hi = __float2bfloat16(v);
    g_cghi[idx] = hi;
    g_cglo[idx] = __float2bfloat16(v - __bfloat162float(hi));
}

// Split W/b -> g_Whi/lo [gate][d][k=288][n=128]; row 257 = bias, rows 258+ = 0
__global__ void k_split_W(const float* __restrict__ Wr, const float* __restrict__ Wu,
                          const float* __restrict__ Wc, const float* __restrict__ br,
                          const float* __restrict__ bu, const float* __restrict__ bc) {
    size_t idx = (size_t)blockIdx.x * 256 + threadIdx.x;
    if (idx >= (size_t)3 * 32 * KP * IS) return;
    int n = idx & 127;
    size_t r = idx >> 7;
    int k = (int)(r % KP); r /= KP;
    int d = (int)(r % 32);
    int g = (int)(r / 32);
    const float* W = (g == 0) ? Wr : (g == 1) ? Wu : Wc;
    const float* b = (g == 0) ? br : (g == 1) ? bu : bc;
    float v = 0.0f;
    if (k < INDIM)       v = W[((size_t)d * INDIM + k) * IS + n];
    else if (k == INDIM) v = b[d * IS + n];
    bf16 hi = __float2bfloat16(v);
    g_Whi[idx] = hi;
    g_Wlo[idx] = __float2bfloat16(v - __bfloat162float(hi));
}

// ---------------------------------------------------------------------------
// Tensor gate GEMM (mma.sync bf16 hi/lo): out_split[m,n] = sum_{d in split}
//   q[m,d] * (A @ W_d)[m,n]   (bias folded into K row 257)
// BM=128, BN=64, 256 thr (8 warps: 4m x 2n of 32x32).
// ---------------------------------------------------------------------------
__global__ __launch_bounds__(256, 2) void k_mma(
    const bf16* __restrict__ Ahi, const bf16* __restrict__ Alo,
    const bf16* __restrict__ Whi, const bf16* __restrict__ Wlo,
    const float* __restrict__ q,
    float* __restrict__ out0, float* __restrict__ out1,
    int ngate, int dper) {
    __shared__ __align__(16) bf16 sA[2][128][40];   // [hi/lo][m][k], 80B rows
    __shared__ __align__(16) bf16 sB[2][32][72];    // [hi/lo][k][n], 144B rows
    __shared__ float qs[128][8];

    int t = threadIdx.x, lane = t & 31, wid = t >> 5;
    int n0 = blockIdx.x * 64;
    int m0 = blockIdx.y * 128;
    int gate  = blockIdx.z % ngate;
    int split = blockIdx.z / ngate;
    int d0 = split * dper;

    for (int e = t; e < 128 * dper; e += 256)
        qs[e / dper][e % dper] = q[(size_t)(m0 + e / dper) * QDIM + d0 + e % dper];

    int mw = wid >> 1, nw = wid & 1;
    uint32_t sAu = (uint32_t)__cvta_generic_to_shared(&sA[0][0][0]);
    uint32_t sBu = (uint32_t)__cvta_generic_to_shared(&sB[0][0][0]);
    uint32_t aBase = sAu + (uint32_t)(((mw * 32 + (lane & 15)) * 40 + (lane >> 4) * 8) * 2);
    uint32_t bBase = sBu + (uint32_t)((lane & 15) * 144 + (nw * 32 + (lane >> 4) * 8) * 2);

    float acc[2][4][4];
#pragma unroll
    for (int mi = 0; mi < 2; mi++)
#pragma unroll
        for (int ni = 0; ni < 4; ni++)
#pragma unroll
            for (int j = 0; j < 4; j++) acc[mi][ni][j] = 0.0f;

    const bf16* WhG = Whi + (size_t)gate * 32 * KP * IS;
    const bf16* WlG = Wlo + (size_t)gate * 32 * KP * IS;

    for (int dj = 0; dj < dper; dj++) {
        int d = d0 + dj;
        const bf16* Wh = WhG + (size_t)d * KP * IS;
        const bf16* Wl = WlG + (size_t)d * KP * IS;
        float c[2][4][4];
#pragma unroll
        for (int mi = 0; mi < 2; mi++)
#pragma unroll
            for (int ni = 0; ni < 4; ni++)
#pragma unroll
                for (int j = 0; j < 4; j++) c[mi][ni][j] = 0.0f;

        for (int kc = 0; kc < KP / 32; kc++) {
            __syncthreads();
            // A chunk: 128m x 32k, hi+lo (2 granules/thread each)
#pragma unroll
            for (int pr = 0; pr < 2; pr++) {
                const bf16* srcA = pr ? Alo : Ahi;
#pragma unroll
                for (int p = 0; p < 2; p++) {
                    int e = t + 256 * p;
                    int row = e >> 2, gg = e & 3;
                    cpa16(sAu + (uint32_t)(pr * 10240 + row * 80 + gg * 16),
                          srcA + (size_t)(m0 + row) * KP + kc * 32 + gg * 8);
                }
            }
            // B chunk: 32k x 64n, hi+lo (1 granule/thread each)
#pragma unroll
            for (int pr = 0; pr < 2; pr++) {
                const bf16* srcB = pr ? Wl : Wh;
                int k = t >> 3, gg = t & 7;
                cpa16(sBu + (uint32_t)(pr * 4608 + k * 144 + gg * 16),
                      srcB + (size_t)(kc * 32 + k) * IS + n0 + gg * 8);
            }
            CP_COMMIT();
            CP_WAIT0();
            __syncthreads();

#pragma unroll
            for (int s = 0; s < 2; s++) {
                uint32_t ah[2][4], al[2][4], bh[2][4], bl[2][4];
#pragma unroll
                for (int mi = 0; mi < 2; mi++) {
                    LDSMX4(ah[mi], aBase + mi * 1280 + s * 32);
                    LDSMX4(al[mi], aBase + 10240 + mi * 1280 + s * 32);
                }
#pragma unroll
                for (int nb = 0; nb < 2; nb++) {
                    LDSMX4T(bh[nb], bBase + s * 2304 + nb * 32);
                    LDSMX4T(bl[nb], bBase + 4608 + s * 2304 + nb * 32);
                }
#pragma unroll
                for (int mi = 0; mi < 2; mi++)
#pragma unroll
                    for (int ni = 0; ni < 4; ni++) {
                        uint32_t* fh = &bh[ni >> 1][(ni & 1) * 2];
                        uint32_t* fl = &bl[ni >> 1][(ni & 1) * 2];
                        MMA(c[mi][ni], ah[mi], fh);
                        MMA(c[mi][ni], al[mi], fh);
                        MMA(c[mi][ni], ah[mi], fl);
                    }
            }
        }
        // epilogue: acc += q[m,d] * C_d
#pragma unroll
        for (int mi = 0; mi < 2; mi++) {
            float q0 = qs[mw * 32 + mi * 16 + (lane >> 2)][dj];
            float q1 = qs[mw * 32 + mi * 16 + 8 + (lane >> 2)][dj];
#pragma unroll
            for (int ni = 0; ni < 4; ni++) {
                acc[mi][ni][0] = fmaf(q0, c[mi][ni][0], acc[mi][ni][0]);
                acc[mi][ni][1] = fmaf(q0, c[mi][ni][1], acc[mi][ni][1]);
                acc[mi][ni][2] = fmaf(q1, c[mi][ni][2], acc[mi][ni][2]);
                acc[mi][ni][3] = fmaf(q1, c[mi][ni][3], acc[mi][ni][3]);
            }
        }
    }

    float* outp = (gate ? out1 : out0) + (size_t)split * Mm * IS;
#pragma unroll
    for (int mi = 0; mi < 2; mi++) {
        int r0 = m0 + mw * 32 + mi * 16 + (lane >> 2);
#pragma unroll
        for (int ni = 0; ni < 4; ni++) {
            int col = n0 + nw * 32 + ni * 8 + (lane & 3) * 2;
            *(float2*)&outp[(size_t)r0 * IS + col] = make_float2(acc[mi][ni][0], acc[mi][ni][1]);
            *(float2*)&outp[(size_t)(r0 + 8) * IS + col] = make_float2(acc[mi][ni][2], acc[mi][ni][3]);
        }
    }
}

// reduce r,u partials (4 splits) + sigmoid
__global__ void k_gates_reduce() {
    int idx = blockIdx.x * 256 + threadIdx.x;
    if (idx >= Mm * IS / 4) return;
    const float4* pr = (const float4*)g_pr;
    const float4* pu = (const float4*)g_pu;
    float4 r = make_float4(0.f, 0.f, 0.f, 0.f);
    float4 u = make_float4(0.f, 0.f, 0.f, 0.f);
#pragma unroll
    for (int s = 0; s < 4; s++) {
        float4 a = pr[idx + (size_t)s * (Mm * IS / 4)];
        float4 b = pu[idx + (size_t)s * (Mm * IS / 4)];
        r.x += a.x; r.y += a.y; r.z += a.z; r.w += a.w;
        u.x += b.x; u.y += b.y; u.z += b.z; u.w += b.w;
    }
    r.x = sigmoidf_(r.x); r.y = sigmoidf_(r.y); r.z = sigmoidf_(r.z); r.w = sigmoidf_(r.w);
    u.x = sigmoidf_(u.x); u.y = sigmoidf_(u.y); u.z = sigmoidf_(u.z); u.w = sigmoidf_(u.w);
    ((float4*)g_r)[idx] = r;
    ((float4*)g_u)[idx] = u;
}

// build cn hi/lo row-major [m][288]; col 257 = 1.0
__global__ void k_pack_cn_split(const float* __restrict__ x, const float* __restrict__ h,
                                const int* __restrict__ nodes) {
    int idx = blockIdx.x * 256 + threadIdx.x;
    if (idx >= Mm * KP) return;
    int m = idx / KP, c = idx - m * KP;
    float v = 0.0f;
    if (c < XC) {
        v = x[(size_t)nodes[m] * XC + c];
    } else if (c < INDIM) {
        int j = c - XC;
        v = g_r[(size_t)m * IS + j] * h[(size_t)nodes[m] * IS + j];
    } else if (c == INDIM) v = 1.0f;
    bf16 hi = __float2bfloat16(v);
    g_cnhi[idx] = hi;
    g_cnlo[idx] = __float2bfloat16(v - __bfloat162float(hi));
}

// reduce candidate partials (16 splits) + tanh + combine
__global__ void k_final_reduce(const float* __restrict__ h,
                               const int* __restrict__ nodes,
                               float* __restrict__ out) {
    int idx = blockIdx.x * 256 + threadIdx.x;
    if (idx >= Mm * IS / 4) return;
    int m  = idx / (IS / 4);
    int c4 = idx - m * (IS / 4);
    int nm = nodes[m];
    const float4* pc = (const float4*)g_pc;
    float4 c = make_float4(0.f, 0.f, 0.f, 0.f);
#pragma unroll
    for (int s = 0; s < 16; s++) {
        float4 a = pc[idx + (size_t)s * (Mm * IS / 4)];
        c.x += a.x; c.y += a.y; c.z += a.z; c.w += a.w;
    }
    float4 rr = ((const float4*)g_r)[idx];
    float4 uu = ((const float4*)g_u)[idx];
    float4 hv = *(const float4*)&h[(size_t)nm * IS + c4 * 4];
    float4 o;
    o.x = (1.0f - uu.x) * rr.x * hv.x + uu.x * tanhf(c.x);
    o.y = (1.0f - uu.y) * rr.y * hv.y + uu.y * tanhf(c.y);
    o.z = (1.0f - uu.z) * rr.z * hv.z + uu.z * tanhf(c.z);
    o.w = (1.0f - uu.w) * rr.w * hv.w + uu.w * tanhf(c.w);
    *(float4*)&out[(size_t)m * IS + c4 * 4] = o;
}

// ---------------------------------------------------------------------------
extern "C" void kernel_launch(void* const* d_in, const int* in_sizes, int n_in,
                              void* d_out, int out_size) {
    const float* x    = (const float*)d_in[0];
    const float* h    = (const float*)d_in[1];
    const float* q    = (const float*)d_in[2];
    const float* adj  = (const float*)d_in[3];
    const int*   nodes= (const int*)  d_in[4];
    const float* Wu   = (const float*)d_in[5];
    const float* bu   = (const float*)d_in[6];
    const float* Wr   = (const float*)d_in[7];
    const float* br   = (const float*)d_in[8];
    const float* Wc   = (const float*)d_in[9];
    const float* bc   = (const float*)d_in[10];
    float* out = (float*)d_out;

    static bf16* whi_p = nullptr;
    static bf16* wlo_p = nullptr;
    if (!whi_p) {
        cudaGetSymbolAddress((void**)&whi_p, g_Whi);
        cudaGetSymbolAddress((void**)&wlo_p, g_Wlo);
    }
    bf16 *cghi_p, *cglo_p, *cnhi_p, *cnlo_p;
    cudaGetSymbolAddress((void**)&cghi_p, g_cghi);
    cudaGetSymbolAddress((void**)&cglo_p, g_cglo);
    cudaGetSymbolAddress((void**)&cnhi_p, g_cnhi);
    cudaGetSymbolAddress((void**)&cnlo_p, g_cnlo);
    float *pr_p, *pu_p, *pc_p;
    cudaGetSymbolAddress((void**)&pr_p, g_pr);
    cudaGetSymbolAddress((void**)&pu_p, g_pu);
    cudaGetSymbolAddress((void**)&pc_p, g_pc);

    k_pack_cat<<<(Nn * CATP + 255) / 256, 256>>>(x, h);
    k_gemm1<<<dim3(3, 16, S_G1), 256>>>(adj, nodes);
    k_g1_reduce_split<<<(Mm * KP + 255) / 256, 256>>>();
    k_split_W<<<(int)(((size_t)3 * 32 * KP * IS + 255) / 256), 256>>>(Wr, Wu, Wc, br, bu, bc);
    // gates r+u: grid.z = gate(2) * dsplit(4), dper=8
    k_mma<<<dim3(2, 16, 8), 256>>>(cghi_p, cglo_p, whi_p, wlo_p, q, pr_p, pu_p, 2, 8);
    k_gates_reduce<<<(Mm * IS / 4 + 255) / 256, 256>>>();
    k_pack_cn_split<<<(Mm * KP + 255) / 256, 256>>>(x, h, nodes);
    // candidate: W slice g=2, dsplit 16, dper=2
    k_mma<<<dim3(2, 16, 16), 256>>>(cnhi_p, cnlo_p,
                                    whi_p + (size_t)2 * 32 * KP * IS,
                                    wlo_p + (size_t)2 * 32 * KP * IS,
                                    q, pc_p, pc_p, 1, 2);
    k_final_reduce<<<(Mm * IS / 4 + 255) / 256, 256>>>(h, nodes, out);
}

// round 9
// speedup vs baseline: 1.6503x; 1.0643x over previous
#include <cuda_runtime.h>
#include <cuda_bf16.h>
#include <math.h>
#include <stdint.h>

#define Nn   4096
#define Mm   2048
#define IS   128
#define XC   129
#define INDIM 257
#define QDIM 32
#define KP   288      // gate-GEMM K (257 + bias col + pad)
#define NB1  320      // gemm1 out width (288 padded to 5*64)

typedef unsigned long long ull;
typedef __nv_bfloat16 bf16;

// Scratch
__device__ __align__(16) bf16 g_cbhi[Nn * NB1];     // cat padded [4096][320]
__device__ __align__(16) bf16 g_cblo[Nn * NB1];
__device__ __align__(16) bf16 g_ajhi[Mm * Nn];      // adj[nodes] [2048][4096]
__device__ __align__(16) bf16 g_ajlo[Mm * Nn];
__device__ float g_pg1 [2 * Mm * NB1];
__device__ __align__(16) bf16 g_cghi[Mm * KP];
__device__ __align__(16) bf16 g_cglo[Mm * KP];
__device__ __align__(16) bf16 g_cnhi[Mm * KP];
__device__ __align__(16) bf16 g_cnlo[Mm * KP];
__device__ __align__(16) bf16 g_Whi[(size_t)3 * 32 * KP * IS];
__device__ __align__(16) bf16 g_Wlo[(size_t)3 * 32 * KP * IS];
__device__ float g_pr [2 * Mm * IS];
__device__ float g_pu [2 * Mm * IS];
__device__ float g_pc [4 * Mm * IS];
__device__ float g_r  [Mm * IS];
__device__ float g_u  [Mm * IS];

__device__ __forceinline__ float sigmoidf_(float v) { return 1.0f / (1.0f + expf(-v)); }
__device__ __forceinline__ void cpa16(uint32_t dst, const void* src) {
    asm volatile("cp.async.ca.shared.global [%0], [%1], 16;" :: "r"(dst), "l"(src));
}
#define CP_COMMIT() asm volatile("cp.async.commit_group;")
#define CP_WAIT0()  asm volatile("cp.async.wait_group 0;")

#define LDSMX4(R, ADDR)                                                       \
    asm volatile("ldmatrix.sync.aligned.m8n8.x4.shared.b16 {%0,%1,%2,%3}, [%4];" \
        : "=r"((R)[0]), "=r"((R)[1]), "=r"((R)[2]), "=r"((R)[3]) : "r"(ADDR))
#define LDSMX4T(R, ADDR)                                                      \
    asm volatile("ldmatrix.sync.aligned.m8n8.x4.trans.shared.b16 {%0,%1,%2,%3}, [%4];" \
        : "=r"((R)[0]), "=r"((R)[1]), "=r"((R)[2]), "=r"((R)[3]) : "r"(ADDR))
#define MMA(C, A, B)                                                          \
    asm volatile("mma.sync.aligned.m16n8k16.row.col.f32.bf16.bf16.f32 "       \
        "{%0,%1,%2,%3}, {%4,%5,%6,%7}, {%8,%9}, {%0,%1,%2,%3};"               \
        : "+f"((C)[0]), "+f"((C)[1]), "+f"((C)[2]), "+f"((C)[3])              \
        : "r"((A)[0]), "r"((A)[1]), "r"((A)[2]), "r"((A)[3]),                 \
          "r"((B)[0]), "r"((B)[1]))

__device__ __forceinline__ void bsplit(float v, bf16& hi, bf16& lo) {
    hi = __float2bfloat16(v);
    lo = __float2bfloat16(v - __bfloat162float(hi));
}

// ---------------------------------------------------------------------------
// cat -> bf16 hi/lo [4096][320]
__global__ void k_cat_split(const float* __restrict__ x, const float* __restrict__ h) {
    int idx = blockIdx.x * 256 + threadIdx.x;
    if (idx >= Nn * NB1) return;
    int row = idx / NB1, c = idx - row * NB1;
    float v = 0.0f;
    if (c < XC)        v = x[row * XC + c];
    else if (c < INDIM) v = h[row * IS + (c - XC)];
    bf16 hi, lo; bsplit(v, hi, lo);
    g_cbhi[idx] = hi; g_cblo[idx] = lo;
}

// adj[nodes] -> bf16 hi/lo [2048][4096], vec4
__global__ void k_adj_split(const float* __restrict__ adj, const int* __restrict__ nodes) {
    int i4 = blockIdx.x * 256 + threadIdx.x;
    if (i4 >= Mm * Nn / 4) return;
    int m = i4 >> 10;                 // 4096/4 = 1024 vec4 per row
    int k4 = (i4 & 1023) * 4;
    float4 v = *(const float4*)&adj[(size_t)nodes[m] * Nn + k4];
    bf16 h[4], l[4];
    bsplit(v.x, h[0], l[0]); bsplit(v.y, h[1], l[1]);
    bsplit(v.z, h[2], l[2]); bsplit(v.w, h[3], l[3]);
    *(ull*)&g_ajhi[(size_t)m * Nn + k4] = *(ull*)h;
    *(ull*)&g_ajlo[(size_t)m * Nn + k4] = *(ull*)l;
}

// ---------------------------------------------------------------------------
// Tensor GEMM1: pg1[s][m][n] = adjB[m, ks:ks+2048] @ catB[ks:ks+2048, n]
// BM=128, BN=64. grid (5, 16, 2), 256 thr, double-buffered.
// ---------------------------------------------------------------------------
__global__ void k_mma_g1() {
    extern __shared__ char sm[];
    uint32_t su = (uint32_t)__cvta_generic_to_shared(sm);
    int t = threadIdx.x, lane = t & 31, wid = t >> 5;
    int n0 = blockIdx.x * 64, m0 = blockIdx.y * 128, ks = blockIdx.z * 2048;
    int mw = wid >> 1, nw = wid & 1;
    uint32_t aB = su + (uint32_t)((mw * 32 + (lane & 15)) * 80 + (lane >> 4) * 16);
    uint32_t bB = su + 40960u + (uint32_t)((lane & 15) * 144 + (nw * 32 + (lane >> 4) * 8) * 2);

    float acc[2][4][4];
#pragma unroll
    for (int mi = 0; mi < 2; mi++)
#pragma unroll
        for (int ni = 0; ni < 4; ni++)
#pragma unroll
            for (int j = 0; j < 4; j++) acc[mi][ni][j] = 0.0f;

#define G1LD(KC, NB)                                                          \
    {                                                                         \
        int _k0 = ks + (KC) * 32;                                             \
        _Pragma("unroll")                                                     \
        for (int pr = 0; pr < 2; pr++) {                                      \
            const bf16* sa = pr ? g_ajlo : g_ajhi;                            \
            _Pragma("unroll")                                                 \
            for (int p = 0; p < 2; p++) {                                     \
                int e = t + 256 * p;                                          \
                int row = e >> 2, gg = e & 3;                                 \
                cpa16(su + (uint32_t)((NB) * 20480 + pr * 10240 + row * 80 + gg * 16), \
                      sa + (size_t)(m0 + row) * Nn + _k0 + gg * 8);           \
            }                                                                 \
            const bf16* sb = pr ? g_cblo : g_cbhi;                            \
            int k = t >> 3, gg2 = t & 7;                                      \
            cpa16(su + (uint32_t)(40960 + (NB) * 9216 + pr * 4608 + k * 144 + gg2 * 16), \
                  sb + (size_t)(_k0 + k) * NB1 + n0 + gg2 * 8);               \
        }                                                                     \
    }

    G1LD(0, 0);
    CP_COMMIT();
    CP_WAIT0();
    __syncthreads();

    for (int it = 0; it < 64; it++) {
        int buf = it & 1, nb = buf ^ 1;
        if (it + 1 < 64) { G1LD(it + 1, nb); CP_COMMIT(); }
#pragma unroll
        for (int s = 0; s < 2; s++) {
            uint32_t ah[2][4], al[2][4], bh[2][4], bl[2][4];
#pragma unroll
            for (int mi = 0; mi < 2; mi++) {
                LDSMX4(ah[mi], aB + buf * 20480 + mi * 1280 + s * 32);
                LDSMX4(al[mi], aB + buf * 20480 + 10240 + mi * 1280 + s * 32);
            }
#pragma unroll
            for (int nbk = 0; nbk < 2; nbk++) {
                LDSMX4T(bh[nbk], bB + buf * 9216 + s * 2304 + nbk * 32);
                LDSMX4T(bl[nbk], bB + buf * 9216 + 4608 + s * 2304 + nbk * 32);
            }
#pragma unroll
            for (int mi = 0; mi < 2; mi++)
#pragma unroll
                for (int ni = 0; ni < 4; ni++) {
                    uint32_t* fh = &bh[ni >> 1][(ni & 1) * 2];
                    uint32_t* fl = &bl[ni >> 1][(ni & 1) * 2];
                    MMA(acc[mi][ni], ah[mi], fh);
                    MMA(acc[mi][ni], al[mi], fh);
                    MMA(acc[mi][ni], ah[mi], fl);
                }
        }
        CP_WAIT0();
        __syncthreads();
    }

    float* dst = g_pg1 + (size_t)blockIdx.z * Mm * NB1;
#pragma unroll
    for (int mi = 0; mi < 2; mi++) {
        int r0 = m0 + mw * 32 + mi * 16 + (lane >> 2);
#pragma unroll
        for (int ni = 0; ni < 4; ni++) {
            int col = n0 + nw * 32 + ni * 8 + (lane & 3) * 2;
            *(float2*)&dst[(size_t)r0 * NB1 + col] = make_float2(acc[mi][ni][0], acc[mi][ni][1]);
            *(float2*)&dst[(size_t)(r0 + 8) * NB1 + col] = make_float2(acc[mi][ni][2], acc[mi][ni][3]);
        }
    }
#undef G1LD
}

// sum 2 k-splits -> cg bf16 hi/lo [2048][288], col 257 = 1.0
__global__ void k_cg_split() {
    int idx = blockIdx.x * 256 + threadIdx.x;
    if (idx >= Mm * KP) return;
    int m = idx / KP, c = idx - m * KP;
    float v = 0.0f;
    if (c < INDIM)
        v = g_pg1[(size_t)m * NB1 + c] + g_pg1[(size_t)(Mm + m) * NB1 + c];
    else if (c == INDIM) v = 1.0f;
    bf16 hi, lo; bsplit(v, hi, lo);
    g_cghi[idx] = hi; g_cglo[idx] = lo;
}

// W/b -> hi/lo [gate][d][k=288][n=128]; row 257 = bias
__global__ void k_split_W(const float* __restrict__ Wr, const float* __restrict__ Wu,
                          const float* __restrict__ Wc, const float* __restrict__ br,
                          const float* __restrict__ bu, const float* __restrict__ bc) {
    size_t idx = (size_t)blockIdx.x * 256 + threadIdx.x;
    if (idx >= (size_t)3 * 32 * KP * IS) return;
    int n = idx & 127;
    size_t r = idx >> 7;
    int k = (int)(r % KP); r /= KP;
    int d = (int)(r % 32);
    int g = (int)(r / 32);
    const float* W = (g == 0) ? Wr : (g == 1) ? Wu : Wc;
    const float* b = (g == 0) ? br : (g == 1) ? bu : bc;
    float v = 0.0f;
    if (k < INDIM)       v = W[((size_t)d * INDIM + k) * IS + n];
    else if (k == INDIM) v = b[d * IS + n];
    bf16 hi, lo; bsplit(v, hi, lo);
    g_Whi[idx] = hi; g_Wlo[idx] = lo;
}

// ---------------------------------------------------------------------------
// Gate GEMM: A persistent in smem (full K=288 hi/lo), B double-buffered.
// out_split[m,n] = sum_{d in split} q[m,d]*(A@W_d)[m,n]; bias in K row 257.
// BM=128, BN=64. dyn smem 169984B (1 CTA/SM).
// ---------------------------------------------------------------------------
__global__ void k_mma2(const bf16* __restrict__ Ahi, const bf16* __restrict__ Alo,
                       const bf16* __restrict__ Whi, const bf16* __restrict__ Wlo,
                       const float* __restrict__ q,
                       float* __restrict__ out0, float* __restrict__ out1,
                       int ngate, int dper) {
    extern __shared__ char sm[];
    __shared__ float qs[128][16];
    uint32_t su = (uint32_t)__cvta_generic_to_shared(sm);
    int t = threadIdx.x, lane = t & 31, wid = t >> 5;
    int n0 = blockIdx.x * 64, m0 = blockIdx.y * 128;
    int gate = blockIdx.z % ngate, split = blockIdx.z / ngate;
    int d0 = split * dper;

    for (int e = t; e < 128 * dper; e += 256)
        qs[e / dper][e % dper] = q[(size_t)(m0 + e / dper) * QDIM + d0 + e % dper];

    int mw = wid >> 1, nw = wid & 1;
    uint32_t aB = su + (uint32_t)((mw * 32 + (lane & 15)) * 592 + (lane >> 4) * 16);
    uint32_t bB = su + 151552u + (uint32_t)((lane & 15) * 144 + (nw * 32 + (lane >> 4) * 8) * 2);

    // load A (full K) once
#pragma unroll
    for (int pr = 0; pr < 2; pr++) {
        const bf16* sa = pr ? Alo : Ahi;
#pragma unroll
        for (int p = 0; p < 18; p++) {
            int e = t + 256 * p;
            int row = e / 36, gg = e - row * 36;
            cpa16(su + (uint32_t)(pr * 75776 + row * 592 + gg * 16),
                  sa + (size_t)(m0 + row) * KP + gg * 8);
        }
    }

#define LDB2(DJ, KC, NB)                                                      \
    {                                                                         \
        int _d = d0 + (DJ);                                                   \
        size_t _wb = (((size_t)gate * 32 + _d) * KP + (KC) * 32) * IS;        \
        int k = t >> 3, gg = t & 7;                                           \
        cpa16(su + (uint32_t)(151552 + (NB) * 9216 + k * 144 + gg * 16),      \
              Whi + _wb + (size_t)k * IS + n0 + gg * 8);                      \
        cpa16(su + (uint32_t)(151552 + (NB) * 9216 + 4608 + k * 144 + gg * 16), \
              Wlo + _wb + (size_t)k * IS + n0 + gg * 8);                      \
    }

    LDB2(0, 0, 0);
    CP_COMMIT();
    CP_WAIT0();
    __syncthreads();

    float acc[2][4][4], c[2][4][4];
#pragma unroll
    for (int mi = 0; mi < 2; mi++)
#pragma unroll
        for (int ni = 0; ni < 4; ni++)
#pragma unroll
            for (int j = 0; j < 4; j++) acc[mi][ni][j] = 0.0f;

    const int J = dper * 9;
    for (int j = 0; j < J; j++) {
        int dj = j / 9, kc = j - dj * 9;
        int buf = j & 1, nb = buf ^ 1;
        if (kc == 0) {
#pragma unroll
            for (int mi = 0; mi < 2; mi++)
#pragma unroll
                for (int ni = 0; ni < 4; ni++)
#pragma unroll
                    for (int jj = 0; jj < 4; jj++) c[mi][ni][jj] = 0.0f;
        }
        if (j + 1 < J) {
            int j2 = j + 1, dj2 = j2 / 9, kc2 = j2 - dj2 * 9;
            LDB2(dj2, kc2, nb);
            CP_COMMIT();
        }
#pragma unroll
        for (int s = 0; s < 2; s++) {
            uint32_t ah[2][4], al[2][4], bh[2][4], bl[2][4];
#pragma unroll
            for (int mi = 0; mi < 2; mi++) {
                LDSMX4(ah[mi], aB + mi * 9472 + kc * 64 + s * 32);
                LDSMX4(al[mi], aB + 75776 + mi * 9472 + kc * 64 + s * 32);
            }
#pragma unroll
            for (int nbk = 0; nbk < 2; nbk++) {
                LDSMX4T(bh[nbk], bB + buf * 9216 + s * 2304 + nbk * 32);
                LDSMX4T(bl[nbk], bB + buf * 9216 + 4608 + s * 2304 + nbk * 32);
            }
#pragma unroll
            for (int mi = 0; mi < 2; mi++)
#pragma unroll
                for (int ni = 0; ni < 4; ni++) {
                    uint32_t* fh = &bh[ni >> 1][(ni & 1) * 2];
                    uint32_t* fl = &bl[ni >> 1][(ni & 1) * 2];
                    MMA(c[mi][ni], ah[mi], fh);
                    MMA(c[mi][ni], al[mi], fh);
                    MMA(c[mi][ni], ah[mi], fl);
                }
        }
        if (kc == 8) {
#pragma unroll
            for (int mi = 0; mi < 2; mi++) {
                float q0 = qs[mw * 32 + mi * 16 + (lane >> 2)][dj];
                float q1 = qs[mw * 32 + mi * 16 + 8 + (lane >> 2)][dj];
#pragma unroll
                for (int ni = 0; ni < 4; ni++) {
                    acc[mi][ni][0] = fmaf(q0, c[mi][ni][0], acc[mi][ni][0]);
                    acc[mi][ni][1] = fmaf(q0, c[mi][ni][1], acc[mi][ni][1]);
                    acc[mi][ni][2] = fmaf(q1, c[mi][ni][2], acc[mi][ni][2]);
                    acc[mi][ni][3] = fmaf(q1, c[mi][ni][3], acc[mi][ni][3]);
                }
            }
        }
        CP_WAIT0();
        __syncthreads();
    }

    float* outp = (gate ? out1 : out0) + (size_t)split * Mm * IS;
#pragma unroll
    for (int mi = 0; mi < 2; mi++) {
        int r0 = m0 + mw * 32 + mi * 16 + (lane >> 2);
#pragma unroll
        for (int ni = 0; ni < 4; ni++) {
            int col = n0 + nw * 32 + ni * 8 + (lane & 3) * 2;
            *(float2*)&outp[(size_t)r0 * IS + col] = make_float2(acc[mi][ni][0], acc[mi][ni][1]);
            *(float2*)&outp[(size_t)(r0 + 8) * IS + col] = make_float2(acc[mi][ni][2], acc[mi][ni][3]);
        }
    }
#undef LDB2
}

// reduce r,u (2 splits) + sigmoid
__global__ void k_gates_reduce() {
    int idx = blockIdx.x * 256 + threadIdx.x;
    if (idx >= Mm * IS / 4) return;
    const float4* pr = (const float4*)g_pr;
    const float4* pu = (const float4*)g_pu;
    float4 a0 = pr[idx], a1 = pr[idx + Mm * IS / 4];
    float4 b0 = pu[idx], b1 = pu[idx + Mm * IS / 4];
    float4 r, u;
    r.x = sigmoidf_(a0.x + a1.x); r.y = sigmoidf_(a0.y + a1.y);
    r.z = sigmoidf_(a0.z + a1.z); r.w = sigmoidf_(a0.w + a1.w);
    u.x = sigmoidf_(b0.x + b1.x); u.y = sigmoidf_(b0.y + b1.y);
    u.z = sigmoidf_(b0.z + b1.z); u.w = sigmoidf_(b0.w + b1.w);
    ((float4*)g_r)[idx] = r;
    ((float4*)g_u)[idx] = u;
}

// cn -> bf16 hi/lo [m][288]; col 257 = 1.0
__global__ void k_pack_cn_split(const float* __restrict__ x, const float* __restrict__ h,
                                const int* __restrict__ nodes) {
    int idx = blockIdx.x * 256 + threadIdx.x;
    if (idx >= Mm * KP) return;
    int m = idx / KP, c = idx - m * KP;
    float v = 0.0f;
    if (c < XC) {
        v = x[(size_t)nodes[m] * XC + c];
    } else if (c < INDIM) {
        int j = c - XC;
        v = g_r[(size_t)m * IS + j] * h[(size_t)nodes[m] * IS + j];
    } else if (c == INDIM) v = 1.0f;
    bf16 hi, lo; bsplit(v, hi, lo);
    g_cnhi[idx] = hi; g_cnlo[idx] = lo;
}

// reduce candidate (4 splits) + tanh + combine
__global__ void k_final_reduce(const float* __restrict__ h,
                               const int* __restrict__ nodes,
                               float* __restrict__ out) {
    int idx = blockIdx.x * 256 + threadIdx.x;
    if (idx >= Mm * IS / 4) return;
    int m  = idx / (IS / 4);
    int c4 = idx - m * (IS / 4);
    int nm = nodes[m];
    const float4* pc = (const float4*)g_pc;
    float4 c = make_float4(0.f, 0.f, 0.f, 0.f);
#pragma unroll
    for (int s = 0; s < 4; s++) {
        float4 a = pc[idx + (size_t)s * (Mm * IS / 4)];
        c.x += a.x; c.y += a.y; c.z += a.z; c.w += a.w;
    }
    float4 rr = ((const float4*)g_r)[idx];
    float4 uu = ((const float4*)g_u)[idx];
    float4 hv = *(const float4*)&h[(size_t)nm * IS + c4 * 4];
    float4 o;
    o.x = (1.0f - uu.x) * rr.x * hv.x + uu.x * tanhf(c.x);
    o.y = (1.0f - uu.y) * rr.y * hv.y + uu.y * tanhf(c.y);
    o.z = (1.0f - uu.z) * rr.z * hv.z + uu.z * tanhf(c.z);
    o.w = (1.0f - uu.w) * rr.w * hv.w + uu.w * tanhf(c.w);
    *(float4*)&out[(size_t)m * IS + c4 * 4] = o;
}

// ---------------------------------------------------------------------------
extern "C" void kernel_launch(void* const* d_in, const int* in_sizes, int n_in,
                              void* d_out, int out_size) {
    const float* x    = (const float*)d_in[0];
    const float* h    = (const float*)d_in[1];
    const float* q    = (const float*)d_in[2];
    const float* adj  = (const float*)d_in[3];
    const int*   nodes= (const int*)  d_in[4];
    const float* Wu   = (const float*)d_in[5];
    const float* bu   = (const float*)d_in[6];
    const float* Wr   = (const float*)d_in[7];
    const float* br   = (const float*)d_in[8];
    const float* Wc   = (const float*)d_in[9];
    const float* bc   = (const float*)d_in[10];
    float* out = (float*)d_out;

    static bool init = false;
    if (!init) {
        cudaFuncSetAttribute(k_mma_g1, cudaFuncAttributeMaxDynamicSharedMemorySize, 59392);
        cudaFuncSetAttribute(k_mma2, cudaFuncAttributeMaxDynamicSharedMemorySize, 169984);
        init = true;
    }

    bf16 *whi_p, *wlo_p, *cghi_p, *cglo_p, *cnhi_p, *cnlo_p;
    cudaGetSymbolAddress((void**)&whi_p, g_Whi);
    cudaGetSymbolAddress((void**)&wlo_p, g_Wlo);
    cudaGetSymbolAddress((void**)&cghi_p, g_cghi);
    cudaGetSymbolAddress((void**)&cglo_p, g_cglo);
    cudaGetSymbolAddress((void**)&cnhi_p, g_cnhi);
    cudaGetSymbolAddress((void**)&cnlo_p, g_cnlo);
    float *pr_p, *pu_p, *pc_p;
    cudaGetSymbolAddress((void**)&pr_p, g_pr);
    cudaGetSymbolAddress((void**)&pu_p, g_pu);
    cudaGetSymbolAddress((void**)&pc_p, g_pc);

    k_cat_split<<<(Nn * NB1 + 255) / 256, 256>>>(x, h);
    k_adj_split<<<(Mm * Nn / 4 + 255) / 256, 256>>>(adj, nodes);
    k_split_W<<<(int)(((size_t)3 * 32 * KP * IS + 255) / 256), 256>>>(Wr, Wu, Wc, br, bu, bc);
    k_mma_g1<<<dim3(5, 16, 2), 256, 59392>>>();
    k_cg_split<<<(Mm * KP + 255) / 256, 256>>>();
    // gates r+u: gate(2) x dsplit(2), dper=16 -> 128 CTAs
    k_mma2<<<dim3(2, 16, 4), 256, 169984>>>(cghi_p, cglo_p, whi_p, wlo_p, q, pr_p, pu_p, 2, 16);
    k_gates_reduce<<<(Mm * IS / 4 + 255) / 256, 256>>>();
    k_pack_cn_split<<<(Mm * KP + 255) / 256, 256>>>(x, h, nodes);
    // candidate: gate slice g=2, dsplit(4), dper=8 -> 128 CTAs
    k_mma2<<<dim3(2, 16, 4), 256, 169984>>>(cnhi_p, cnlo_p,
                                            whi_p + (size_t)2 * 32 * KP * IS,
                                            wlo_p + (size_t)2 * 32 * KP * IS,
                                            q, pc_p, pc_p, 1, 8);
    k_final_reduce<<<(Mm * IS / 4 + 255) / 256, 256>>>(h, nodes, out);
}

// round 11
// speedup vs baseline: 1.7957x; 1.0881x over previous
#include <cuda_runtime.h>
#include <cuda_bf16.h>
#include <math.h>
#include <stdint.h>

#define Nn   4096
#define Mm   2048
#define IS   128
#define XC   129
#define INDIM 257
#define QDIM 32
#define KP   288      // gate-GEMM K (257 + bias col + pad)
#define NB1  320      // gemm1 out width

typedef unsigned long long ull;
typedef __nv_bfloat16 bf16;

// Scratch
__device__ __align__(16) bf16 g_cbhi[Nn * NB1];
__device__ __align__(16) bf16 g_cblo[Nn * NB1];
__device__ __align__(16) bf16 g_ajhi[Mm * Nn];
__device__ __align__(16) bf16 g_ajlo[Mm * Nn];
__device__ float g_pg1 [4 * Mm * NB1];
__device__ __align__(16) bf16 g_cghi[Mm * KP];
__device__ __align__(16) bf16 g_cglo[Mm * KP];
__device__ __align__(16) bf16 g_cnhi[Mm * KP];
__device__ __align__(16) bf16 g_cnlo[Mm * KP];
__device__ __align__(16) bf16 g_Whi[(size_t)3 * 32 * KP * IS];
__device__ __align__(16) bf16 g_Wlo[(size_t)3 * 32 * KP * IS];
__device__ float g_pr [4 * Mm * IS];
__device__ float g_pu [4 * Mm * IS];
__device__ float g_pc [8 * Mm * IS];
__device__ float g_r  [Mm * IS];
__device__ float g_u  [Mm * IS];

__device__ __forceinline__ float sigmoidf_(float v) { return 1.0f / (1.0f + expf(-v)); }
__device__ __forceinline__ void cpa16(uint32_t dst, const void* src) {
    asm volatile("cp.async.ca.shared.global [%0], [%1], 16;" :: "r"(dst), "l"(src));
}
#define CP_COMMIT() asm volatile("cp.async.commit_group;")
#define CP_WAIT0()  asm volatile("cp.async.wait_group 0;")

#define LDSMX4(R, ADDR)                                                       \
    asm volatile("ldmatrix.sync.aligned.m8n8.x4.shared.b16 {%0,%1,%2,%3}, [%4];" \
        : "=r"((R)[0]), "=r"((R)[1]), "=r"((R)[2]), "=r"((R)[3]) : "r"(ADDR))
#define LDSMX4T(R, ADDR)                                                      \
    asm volatile("ldmatrix.sync.aligned.m8n8.x4.trans.shared.b16 {%0,%1,%2,%3}, [%4];" \
        : "=r"((R)[0]), "=r"((R)[1]), "=r"((R)[2]), "=r"((R)[3]) : "r"(ADDR))
#define MMA(C, A, B)                                                          \
    asm volatile("mma.sync.aligned.m16n8k16.row.col.f32.bf16.bf16.f32 "       \
        "{%0,%1,%2,%3}, {%4,%5,%6,%7}, {%8,%9}, {%0,%1,%2,%3};"               \
        : "+f"((C)[0]), "+f"((C)[1]), "+f"((C)[2]), "+f"((C)[3])              \
        : "r"((A)[0]), "r"((A)[1]), "r"((A)[2]), "r"((A)[3]),                 \
          "r"((B)[0]), "r"((B)[1]))

__device__ __forceinline__ void bsplit(float v, bf16& hi, bf16& lo) {
    hi = __float2bfloat16(v);
    lo = __float2bfloat16(v - __bfloat162float(hi));
}

// ---------------------------------------------------------------------------
__global__ void k_cat_split(const float* __restrict__ x, const float* __restrict__ h) {
    int idx = blockIdx.x * 256 + threadIdx.x;
    if (idx >= Nn * NB1) return;
    int row = idx / NB1, c = idx - row * NB1;
    float v = 0.0f;
    if (c < XC)        v = x[row * XC + c];
    else if (c < INDIM) v = h[row * IS + (c - XC)];
    bf16 hi, lo; bsplit(v, hi, lo);
    g_cbhi[idx] = hi; g_cblo[idx] = lo;
}

__global__ void k_adj_split(const float* __restrict__ adj, const int* __restrict__ nodes) {
    int i4 = blockIdx.x * 256 + threadIdx.x;
    if (i4 >= Mm * Nn / 4) return;
    int m = i4 >> 10;
    int k4 = (i4 & 1023) * 4;
    float4 v = *(const float4*)&adj[(size_t)nodes[m] * Nn + k4];
    bf16 h[4], l[4];
    bsplit(v.x, h[0], l[0]); bsplit(v.y, h[1], l[1]);
    bsplit(v.z, h[2], l[2]); bsplit(v.w, h[3], l[3]);
    *(ull*)&g_ajhi[(size_t)m * Nn + k4] = *(ull*)h;
    *(ull*)&g_ajlo[(size_t)m * Nn + k4] = *(ull*)l;
}

// ---------------------------------------------------------------------------
// Tensor GEMM1: BM=128, BN=64, K-split 4 (1024 each). grid (5, 16, 4), 2 CTA/SM.
// ---------------------------------------------------------------------------
__global__ __launch_bounds__(256, 2) void k_mma_g1() {
    extern __shared__ char sm[];
    uint32_t su = (uint32_t)__cvta_generic_to_shared(sm);
    int t = threadIdx.x, lane = t & 31, wid = t >> 5;
    int n0 = blockIdx.x * 64, m0 = blockIdx.y * 128, ks = blockIdx.z * 1024;
    int mw = wid >> 1, nw = wid & 1;
    uint32_t aB = su + (uint32_t)((mw * 32 + (lane & 15)) * 80 + (lane >> 4) * 16);
    uint32_t bB = su + 40960u + (uint32_t)((lane & 15) * 144 + (nw * 32 + (lane >> 4) * 8) * 2);

    float acc[2][4][4];
#pragma unroll
    for (int mi = 0; mi < 2; mi++)
#pragma unroll
        for (int ni = 0; ni < 4; ni++)
#pragma unroll
            for (int j = 0; j < 4; j++) acc[mi][ni][j] = 0.0f;

#define G1LD(KC, NB)                                                          \
    {                                                                         \
        int _k0 = ks + (KC) * 32;                                             \
        _Pragma("unroll")                                                     \
        for (int pr = 0; pr < 2; pr++) {                                      \
            const bf16* sa = pr ? g_ajlo : g_ajhi;                            \
            _Pragma("unroll")                                                 \
            for (int p = 0; p < 2; p++) {                                     \
                int e = t + 256 * p;                                          \
                int row = e >> 2, gg = e & 3;                                 \
                cpa16(su + (uint32_t)((NB) * 20480 + pr * 10240 + row * 80 + gg * 16), \
                      sa + (size_t)(m0 + row) * Nn + _k0 + gg * 8);           \
            }                                                                 \
            const bf16* sb = pr ? g_cblo : g_cbhi;                            \
            int k = t >> 3, gg2 = t & 7;                                      \
            cpa16(su + (uint32_t)(40960 + (NB) * 9216 + pr * 4608 + k * 144 + gg2 * 16), \
                  sb + (size_t)(_k0 + k) * NB1 + n0 + gg2 * 8);               \
        }                                                                     \
    }

    G1LD(0, 0);
    CP_COMMIT();
    CP_WAIT0();
    __syncthreads();

    for (int it = 0; it < 32; it++) {
        int buf = it & 1, nb = buf ^ 1;
        if (it + 1 < 32) { G1LD(it + 1, nb); CP_COMMIT(); }
#pragma unroll
        for (int s = 0; s < 2; s++) {
            uint32_t ah[2][4], al[2][4], bh[2][4], bl[2][4];
#pragma unroll
            for (int mi = 0; mi < 2; mi++) {
                LDSMX4(ah[mi], aB + buf * 20480 + mi * 1280 + s * 32);
                LDSMX4(al[mi], aB + buf * 20480 + 10240 + mi * 1280 + s * 32);
            }
#pragma unroll
            for (int nbk = 0; nbk < 2; nbk++) {
                LDSMX4T(bh[nbk], bB + buf * 9216 + s * 2304 + nbk * 32);
                LDSMX4T(bl[nbk], bB + buf * 9216 + 4608 + s * 2304 + nbk * 32);
            }
#pragma unroll
            for (int mi = 0; mi < 2; mi++)
#pragma unroll
                for (int ni = 0; ni < 4; ni++) {
                    uint32_t* fh = &bh[ni >> 1][(ni & 1) * 2];
                    uint32_t* fl = &bl[ni >> 1][(ni & 1) * 2];
                    MMA(acc[mi][ni], ah[mi], fh);
                    MMA(acc[mi][ni], al[mi], fh);
                    MMA(acc[mi][ni], ah[mi], fl);
                }
        }
        CP_WAIT0();
        __syncthreads();
    }

    float* dst = g_pg1 + (size_t)blockIdx.z * Mm * NB1;
#pragma unroll
    for (int mi = 0; mi < 2; mi++) {
        int r0 = m0 + mw * 32 + mi * 16 + (lane >> 2);
#pragma unroll
        for (int ni = 0; ni < 4; ni++) {
            int col = n0 + nw * 32 + ni * 8 + (lane & 3) * 2;
            *(float2*)&dst[(size_t)r0 * NB1 + col] = make_float2(acc[mi][ni][0], acc[mi][ni][1]);
            *(float2*)&dst[(size_t)(r0 + 8) * NB1 + col] = make_float2(acc[mi][ni][2], acc[mi][ni][3]);
        }
    }
#undef G1LD
}

// sum 4 k-splits -> cg bf16 hi/lo; col 257 = 1.0
__global__ void k_cg_split() {
    int idx = blockIdx.x * 256 + threadIdx.x;
    if (idx >= Mm * KP) return;
    int m = idx / KP, c = idx - m * KP;
    float v = 0.0f;
    if (c < INDIM) {
#pragma unroll
        for (int s = 0; s < 4; s++)
            v += g_pg1[(size_t)s * Mm * NB1 + (size_t)m * NB1 + c];
    } else if (c == INDIM) v = 1.0f;
    bf16 hi, lo; bsplit(v, hi, lo);
    g_cghi[idx] = hi; g_cglo[idx] = lo;
}

__global__ void k_split_W(const float* __restrict__ Wr, const float* __restrict__ Wu,
                          const float* __restrict__ Wc, const float* __restrict__ br,
                          const float* __restrict__ bu, const float* __restrict__ bc) {
    size_t idx = (size_t)blockIdx.x * 256 + threadIdx.x;
    if (idx >= (size_t)3 * 32 * KP * IS) return;
    int n = idx & 127;
    size_t r = idx >> 7;
    int k = (int)(r % KP); r /= KP;
    int d = (int)(r % 32);
    int g = (int)(r / 32);
    const float* W = (g == 0) ? Wr : (g == 1) ? Wu : Wc;
    const float* b = (g == 0) ? br : (g == 1) ? bu : bc;
    float v = 0.0f;
    if (k < INDIM)       v = W[((size_t)d * INDIM + k) * IS + n];
    else if (k == INDIM) v = b[d * IS + n];
    bf16 hi, lo; bsplit(v, hi, lo);
    g_Whi[idx] = hi; g_Wlo[idx] = lo;
}

// ---------------------------------------------------------------------------
// Gate GEMM: A K-slice persistent in smem, B double-buffered, 2 CTA/SM.
// z = gate + ngate*(kspl + 2*dspl). kspl0: chunks 0-4, kspl1: chunks 5-8.
// A smem: 128 rows x 336B stride; hi 0..43008, lo 43008..86016; B at 86016.
// dyn smem 104448. 16-row ldmatrix step = 16*336 = 5376 bytes.
// ---------------------------------------------------------------------------
__global__ __launch_bounds__(256, 2) void k_mma2(
    const bf16* __restrict__ Ahi, const bf16* __restrict__ Alo,
    const bf16* __restrict__ Whi, const bf16* __restrict__ Wlo,
    const float* __restrict__ q,
    float* __restrict__ out0, float* __restrict__ out1,
    int ngate, int dper) {
    extern __shared__ char sm[];
    __shared__ float qs[128][16];
    uint32_t su = (uint32_t)__cvta_generic_to_shared(sm);
    int t = threadIdx.x, lane = t & 31, wid = t >> 5;
    int n0 = blockIdx.x * 64, m0 = blockIdx.y * 128;
    int gate = blockIdx.z % ngate;
    int rest = blockIdx.z / ngate;
    int kspl = rest & 1, dspl = rest >> 1;
    int d0 = dspl * dper;
    int kc0 = kspl ? 5 : 0, nkc = kspl ? 4 : 5;

    for (int e = t; e < 128 * dper; e += 256)
        qs[e / dper][e % dper] = q[(size_t)(m0 + e / dper) * QDIM + d0 + e % dper];

    int mw = wid >> 1, nw = wid & 1;
    uint32_t aB = su + (uint32_t)((mw * 32 + (lane & 15)) * 336 + (lane >> 4) * 16);
    uint32_t bB = su + 86016u + (uint32_t)((lane & 15) * 144 + (nw * 32 + (lane >> 4) * 8) * 2);

    // load A K-slice once (hi+lo)
    int gr = nkc * 4;   // 16B granules per row
#pragma unroll
    for (int pr = 0; pr < 2; pr++) {
        const bf16* sa = pr ? Alo : Ahi;
        for (int g = t; g < 128 * gr; g += 256) {
            int row = g / gr, gg = g - row * gr;
            cpa16(su + (uint32_t)(pr * 43008 + row * 336 + gg * 16),
                  sa + (size_t)(m0 + row) * KP + kc0 * 32 + gg * 8);
        }
    }

#define LDB2(DJ, KC, NB)                                                      \
    {                                                                         \
        int _d = d0 + (DJ);                                                   \
        size_t _wb = (((size_t)gate * 32 + _d) * KP + (kc0 + (KC)) * 32) * IS; \
        int k = t >> 3, gg = t & 7;                                           \
        cpa16(su + (uint32_t)(86016 + (NB) * 9216 + k * 144 + gg * 16),       \
              Whi + _wb + (size_t)k * IS + n0 + gg * 8);                      \
        cpa16(su + (uint32_t)(86016 + (NB) * 9216 + 4608 + k * 144 + gg * 16), \
              Wlo + _wb + (size_t)k * IS + n0 + gg * 8);                      \
    }

    LDB2(0, 0, 0);
    CP_COMMIT();
    CP_WAIT0();
    __syncthreads();

    float acc[2][4][4], c[2][4][4];
#pragma unroll
    for (int mi = 0; mi < 2; mi++)
#pragma unroll
        for (int ni = 0; ni < 4; ni++)
#pragma unroll
            for (int j = 0; j < 4; j++) acc[mi][ni][j] = 0.0f;

    const int J = dper * nkc;
    for (int j = 0; j < J; j++) {
        int dj = j / nkc, kc = j - dj * nkc;
        int buf = j & 1, nb = buf ^ 1;
        if (kc == 0) {
#pragma unroll
            for (int mi = 0; mi < 2; mi++)
#pragma unroll
                for (int ni = 0; ni < 4; ni++)
#pragma unroll
                    for (int jj = 0; jj < 4; jj++) c[mi][ni][jj] = 0.0f;
        }
        if (j + 1 < J) {
            int j2 = j + 1, dj2 = j2 / nkc, kc2 = j2 - dj2 * nkc;
            LDB2(dj2, kc2, nb);
            CP_COMMIT();
        }
#pragma unroll
        for (int s = 0; s < 2; s++) {
            uint32_t ah[2][4], al[2][4], bh[2][4], bl[2][4];
#pragma unroll
            for (int mi = 0; mi < 2; mi++) {
                LDSMX4(ah[mi], aB + mi * 5376 + kc * 64 + s * 32);
                LDSMX4(al[mi], aB + 43008 + mi * 5376 + kc * 64 + s * 32);
            }
#pragma unroll
            for (int nbk = 0; nbk < 2; nbk++) {
                LDSMX4T(bh[nbk], bB + buf * 9216 + s * 2304 + nbk * 32);
                LDSMX4T(bl[nbk], bB + buf * 9216 + 4608 + s * 2304 + nbk * 32);
            }
#pragma unroll
            for (int mi = 0; mi < 2; mi++)
#pragma unroll
                for (int ni = 0; ni < 4; ni++) {
                    uint32_t* fh = &bh[ni >> 1][(ni & 1) * 2];
                    uint32_t* fl = &bl[ni >> 1][(ni & 1) * 2];
                    MMA(c[mi][ni], ah[mi], fh);
                    MMA(c[mi][ni], al[mi], fh);
                    MMA(c[mi][ni], ah[mi], fl);
                }
        }
        if (kc == nkc - 1) {
#pragma unroll
            for (int mi = 0; mi < 2; mi++) {
                float q0 = qs[mw * 32 + mi * 16 + (lane >> 2)][dj];
                float q1 = qs[mw * 32 + mi * 16 + 8 + (lane >> 2)][dj];
#pragma unroll
                for (int ni = 0; ni < 4; ni++) {
                    acc[mi][ni][0] = fmaf(q0, c[mi][ni][0], acc[mi][ni][0]);
                    acc[mi][ni][1] = fmaf(q0, c[mi][ni][1], acc[mi][ni][1]);
                    acc[mi][ni][2] = fmaf(q1, c[mi][ni][2], acc[mi][ni][2]);
                    acc[mi][ni][3] = fmaf(q1, c[mi][ni][3], acc[mi][ni][3]);
                }
            }
        }
        CP_WAIT0();
        __syncthreads();
    }

    float* outp = (gate ? out1 : out0) + (size_t)rest * Mm * IS;
#pragma unroll
    for (int mi = 0; mi < 2; mi++) {
        int r0 = m0 + mw * 32 + mi * 16 + (lane >> 2);
#pragma unroll
        for (int ni = 0; ni < 4; ni++) {
            int col = n0 + nw * 32 + ni * 8 + (lane & 3) * 2;
            *(float2*)&outp[(size_t)r0 * IS + col] = make_float2(acc[mi][ni][0], acc[mi][ni][1]);
            *(float2*)&outp[(size_t)(r0 + 8) * IS + col] = make_float2(acc[mi][ni][2], acc[mi][ni][3]);
        }
    }
#undef LDB2
}

// reduce r,u (4 partials) + sigmoid
__global__ void k_gates_reduce() {
    int idx = blockIdx.x * 256 + threadIdx.x;
    if (idx >= Mm * IS / 4) return;
    const float4* pr = (const float4*)g_pr;
    const float4* pu = (const float4*)g_pu;
    float4 r = make_float4(0.f, 0.f, 0.f, 0.f);
    float4 u = make_float4(0.f, 0.f, 0.f, 0.f);
#pragma unroll
    for (int s = 0; s < 4; s++) {
        float4 a = pr[idx + (size_t)s * (Mm * IS / 4)];
        float4 b = pu[idx + (size_t)s * (Mm * IS / 4)];
        r.x += a.x; r.y += a.y; r.z += a.z; r.w += a.w;
        u.x += b.x; u.y += b.y; u.z += b.z; u.w += b.w;
    }
    r.x = sigmoidf_(r.x); r.y = sigmoidf_(r.y); r.z = sigmoidf_(r.z); r.w = sigmoidf_(r.w);
    u.x = sigmoidf_(u.x); u.y = sigmoidf_(u.y); u.z = sigmoidf_(u.z); u.w = sigmoidf_(u.w);
    ((float4*)g_r)[idx] = r;
    ((float4*)g_u)[idx] = u;
}

__global__ void k_pack_cn_split(const float* __restrict__ x, const float* __restrict__ h,
                                const int* __restrict__ nodes) {
    int idx = blockIdx.x * 256 + threadIdx.x;
    if (idx >= Mm * KP) return;
    int m = idx / KP, c = idx - m * KP;
    float v = 0.0f;
    if (c < XC) {
        v = x[(size_t)nodes[m] * XC + c];
    } else if (c < INDIM) {
        int j = c - XC;
        v = g_r[(size_t)m * IS + j] * h[(size_t)nodes[m] * IS + j];
    } else if (c == INDIM) v = 1.0f;
    bf16 hi, lo; bsplit(v, hi, lo);
    g_cnhi[idx] = hi; g_cnlo[idx] = lo;
}

// reduce candidate (8 partials) + tanh + combine
__global__ void k_final_reduce(const float* __restrict__ h,
                               const int* __restrict__ nodes,
                               float* __restrict__ out) {
    int idx = blockIdx.x * 256 + threadIdx.x;
    if (idx >= Mm * IS / 4) return;
    int m  = idx / (IS / 4);
    int c4 = idx - m * (IS / 4);
    int nm = nodes[m];
    const float4* pc = (const float4*)g_pc;
    float4 c = make_float4(0.f, 0.f, 0.f, 0.f);
#pragma unroll
    for (int s = 0; s < 8; s++) {
        float4 a = pc[idx + (size_t)s * (Mm * IS / 4)];
        c.x += a.x; c.y += a.y; c.z += a.z; c.w += a.w;
    }
    float4 rr = ((const float4*)g_r)[idx];
    float4 uu = ((const float4*)g_u)[idx];
    float4 hv = *(const float4*)&h[(size_t)nm * IS + c4 * 4];
    float4 o;
    o.x = (1.0f - uu.x) * rr.x * hv.x + uu.x * tanhf(c.x);
    o.y = (1.0f - uu.y) * rr.y * hv.y + uu.y * tanhf(c.y);
    o.z = (1.0f - uu.z) * rr.z * hv.z + uu.z * tanhf(c.z);
    o.w = (1.0f - uu.w) * rr.w * hv.w + uu.w * tanhf(c.w);
    *(float4*)&out[(size_t)m * IS + c4 * 4] = o;
}

// ---------------------------------------------------------------------------
extern "C" void kernel_launch(void* const* d_in, const int* in_sizes, int n_in,
                              void* d_out, int out_size) {
    const float* x    = (const float*)d_in[0];
    const float* h    = (const float*)d_in[1];
    const float* q    = (const float*)d_in[2];
    const float* adj  = (const float*)d_in[3];
    const int*   nodes= (const int*)  d_in[4];
    const float* Wu   = (const float*)d_in[5];
    const float* bu   = (const float*)d_in[6];
    const float* Wr   = (const float*)d_in[7];
    const float* br   = (const float*)d_in[8];
    const float* Wc   = (const float*)d_in[9];
    const float* bc   = (const float*)d_in[10];
    float* out = (float*)d_out;

    static bool init = false;
    if (!init) {
        cudaFuncSetAttribute(k_mma_g1, cudaFuncAttributeMaxDynamicSharedMemorySize, 59392);
        cudaFuncSetAttribute(k_mma2, cudaFuncAttributeMaxDynamicSharedMemorySize, 104448);
        init = true;
    }

    bf16 *whi_p, *wlo_p, *cghi_p, *cglo_p, *cnhi_p, *cnlo_p;
    cudaGetSymbolAddress((void**)&whi_p, g_Whi);
    cudaGetSymbolAddress((void**)&wlo_p, g_Wlo);
    cudaGetSymbolAddress((void**)&cghi_p, g_cghi);
    cudaGetSymbolAddress((void**)&cglo_p, g_cglo);
    cudaGetSymbolAddress((void**)&cnhi_p, g_cnhi);
    cudaGetSymbolAddress((void**)&cnlo_p, g_cnlo);
    float *pr_p, *pu_p, *pc_p;
    cudaGetSymbolAddress((void**)&pr_p, g_pr);
    cudaGetSymbolAddress((void**)&pu_p, g_pu);
    cudaGetSymbolAddress((void**)&pc_p, g_pc);

    k_cat_split<<<(Nn * NB1 + 255) / 256, 256>>>(x, h);
    k_adj_split<<<(Mm * Nn / 4 + 255) / 256, 256>>>(adj, nodes);
    k_split_W<<<(int)(((size_t)3 * 32 * KP * IS + 255) / 256), 256>>>(Wr, Wu, Wc, br, bu, bc);
    k_mma_g1<<<dim3(5, 16, 4), 256, 59392>>>();
    k_cg_split<<<(Mm * KP + 255) / 256, 256>>>();
    // gates r+u: z = gate(2) x (kspl(2) x dspl(2)), dper=16 -> 256 CTAs
    k_mma2<<<dim3(2, 16, 8), 256, 104448>>>(cghi_p, cglo_p, whi_p, wlo_p, q, pr_p, pu_p, 2, 16);
    k_gates_reduce<<<(Mm * IS / 4 + 255) / 256, 256>>>();
    k_pack_cn_split<<<(Mm * KP + 255) / 256, 256>>>(x, h, nodes);
    // candidate: z = kspl(2) x dspl(4), dper=8 -> 256 CTAs
    k_mma2<<<dim3(2, 16, 8), 256, 104448>>>(cnhi_p, cnlo_p,
                                            whi_p + (size_t)2 * 32 * KP * IS,
                                            wlo_p + (size_t)2 * 32 * KP * IS,
                                            q, pc_p, pc_p, 1, 8);
    k_final_reduce<<<(Mm * IS / 4 + 255) / 256, 256>>>(h, nodes, out);
}